// round 14
// baseline (speedup 1.0000x reference)
#include <cuda_runtime.h>
#include <cstdint>
#include <mma.h>
#include <math.h>

using namespace nvcuda;

// Problem constants
#define BB 4
#define TT 2048
#define CC 1024
#define HH 16
#define DD 64
#define MM (BB*TT)          // 8192 rows
#define NQKV (3*CC)         // 3072

// Scratch (device globals; no allocations allowed)
__device__ float g_q[(size_t)BB*HH*TT*DD];
__device__ float g_k[(size_t)BB*HH*TT*DD];
__device__ float g_v[(size_t)BB*HH*TT*DD];
__device__ float g_y[(size_t)MM*CC];

using FragA  = wmma::fragment<wmma::matrix_a, 16,16,8, wmma::precision::tf32, wmma::row_major>;
using FragB  = wmma::fragment<wmma::matrix_b, 16,16,8, wmma::precision::tf32, wmma::row_major>;
using FragBc = wmma::fragment<wmma::matrix_b, 16,16,8, wmma::precision::tf32, wmma::col_major>;
using FragC  = wmma::fragment<wmma::accumulator, 16,16,8, float>;

template <class F>
__device__ __forceinline__ void to_tf32(F& f) {
#pragma unroll
    for (int t = 0; t < f.num_elements; t++) f.x[t] = wmma::__float_to_tf32(f.x[t]);
}

__device__ __forceinline__ void cp_async16(float* smem_dst, const float* gmem_src) {
    uint32_t s = (uint32_t)__cvta_generic_to_shared(smem_dst);
    asm volatile("cp.async.cg.shared.global [%0], [%1], 16;\n" :: "r"(s), "l"(gmem_src));
}
#define CP_ASYNC_COMMIT() asm volatile("cp.async.commit_group;\n" ::: "memory")
#define CP_ASYNC_WAIT0()  asm volatile("cp.async.wait_group 0;\n" ::: "memory")
#define CP_ASYNC_WAIT1()  asm volatile("cp.async.wait_group 1;\n" ::: "memory")

// ---------------------------------------------------------------------------
// GEMM: C[M,N] = A[M,K=1024] * W[K, N] (row-major W, ldb = N)
// mode 0: N=3072, scatter into g_q/g_k/g_v as [B,H,T,D]
// mode 1: N=1024, store to Cout row-major [M, 1024]
// Block tile 128x128, BK=32, 8 warps in 4(m) x 2(n), warp tile 32x64.
// cp.async double-buffered mainloop; one barrier per K-step.
// ---------------------------------------------------------------------------
#define AS_STRIDE 40
#define BS_STRIDE 136
#define AS_BUF (128*AS_STRIDE)           // 5120 floats
#define BS_BUF (32*BS_STRIDE)            // 4352 floats
#define GEMM_SMEM_FLOATS (2*AS_BUF + 2*BS_BUF)
#define GEMM_SMEM_BYTES  (GEMM_SMEM_FLOATS*4)

__global__ void __launch_bounds__(256)
gemm_kernel(const float* __restrict__ A, const float* __restrict__ W,
            int ldb, float* __restrict__ Cout, int mode)
{
    extern __shared__ __align__(16) float gsmem[];
    float* As = gsmem;                   // [2][128][AS_STRIDE]
    float* Bs = gsmem + 2*AS_BUF;        // [2][32][BS_STRIDE]

    const float* Ap = A ? A : g_y;

    const int tid  = threadIdx.x;
    const int lane = tid & 31;
    const int w    = tid >> 5;
    const int wm   = w & 3;
    const int wn   = w >> 2;
    const int m0   = blockIdx.y * 128;
    const int n0   = blockIdx.x * 128;
    const int K    = 1024;

    FragC acc[2][4];
#pragma unroll
    for (int i = 0; i < 2; i++)
#pragma unroll
        for (int j = 0; j < 4; j++) wmma::fill_fragment(acc[i][j], 0.0f);

    const int ar = tid >> 3;
    const int ac = (tid & 7) * 4;
    const int bc = lane * 4;

    auto issue_tile = [&](int kt, int buf) {
        const int k0 = kt * 32;
        float* Ab = As + buf * AS_BUF;
        float* Bb = Bs + buf * BS_BUF;
#pragma unroll
        for (int p = 0; p < 4; p++) {
            cp_async16(&Ab[(ar + 32 * p) * AS_STRIDE + ac],
                       &Ap[(size_t)(m0 + ar + 32 * p) * K + k0 + ac]);
        }
#pragma unroll
        for (int p = 0; p < 4; p++) {
            cp_async16(&Bb[(w + 8 * p) * BS_STRIDE + bc],
                       &W[(size_t)(k0 + w + 8 * p) * ldb + n0 + bc]);
        }
    };

    issue_tile(0, 0);
    CP_ASYNC_COMMIT();
    CP_ASYNC_WAIT0();
    __syncthreads();

    const int NKT = K / 32;
    for (int kt = 0; kt < NKT; kt++) {
        const int cur = kt & 1;

        if (kt + 1 < NKT) {
            issue_tile(kt + 1, cur ^ 1);
            CP_ASYNC_COMMIT();
        }

        float* Ab = As + cur * AS_BUF;
        float* Bb = Bs + cur * BS_BUF;
#pragma unroll
        for (int ks = 0; ks < 4; ks++) {
            FragA af[2];
            FragB bf[4];
#pragma unroll
            for (int i = 0; i < 2; i++) {
                wmma::load_matrix_sync(af[i], &Ab[(wm * 32 + i * 16) * AS_STRIDE + ks * 8], AS_STRIDE);
                to_tf32(af[i]);
            }
#pragma unroll
            for (int j = 0; j < 4; j++) {
                wmma::load_matrix_sync(bf[j], &Bb[(ks * 8) * BS_STRIDE + wn * 64 + j * 16], BS_STRIDE);
                to_tf32(bf[j]);
            }
#pragma unroll
            for (int i = 0; i < 2; i++)
#pragma unroll
                for (int j = 0; j < 4; j++)
                    wmma::mma_sync(acc[i][j], af[i], bf[j], acc[i][j]);
        }

        CP_ASYNC_WAIT0();
        __syncthreads();
    }

    // Epilogue
#pragma unroll
    for (int i = 0; i < 2; i++) {
#pragma unroll
        for (int j = 0; j < 4; j++) {
            int m = m0 + wm * 32 + i * 16;
            int n = n0 + wn * 64 + j * 16;
            if (mode == 1) {
                wmma::store_matrix_sync(&Cout[(size_t)m * 1024 + n], acc[i][j],
                                        1024, wmma::mem_row_major);
            } else {
                int which = n >> 10;          // 0=q 1=k 2=v
                int c = n & 1023;
                int h = c >> 6;
                int d = c & 63;
                int b = m >> 11;
                int t = m & 2047;
                float* base = (which == 0) ? g_q : (which == 1) ? g_k : g_v;
                float* dst = base + ((size_t)(b * HH + h) * TT + t) * DD + d;
                wmma::store_matrix_sync(dst, acc[i][j], 64, wmma::mem_row_major);
            }
        }
    }
}

// ---------------------------------------------------------------------------
// Flash-style causal attention. One block = (b, h, 64-row q tile), 4 warps.
// Dynamic SMEM (floats): sS[64][68], sO[64][68], sK[64][68], sV[64][68],
// sM[64], sL[64]  (~69.9 KB -> 3 CTAs/SM).
// Pipeline per kv-tile j:
//   [K(j) resident]  S = Q K^T  -> sS ; barrier A
//   issue cp.async V(j)->sV (group), K(j+1 clamped)->sK (group)
//   softmax on sS/sO (overlaps both copies)
//   wait_group 1 (V resident) ; barrier B
//   O += P V from sV ; wait_group 0 (K resident) ; barrier C
// K prefetch index clamped to min(j+1, i): uniform group accounting, no OOB.
// ---------------------------------------------------------------------------
#define LDP 68
#define TBUF (64*LDP)
#define ATTN_SMEM_FLOATS (4*TBUF + 128)
#define ATTN_SMEM_BYTES  (ATTN_SMEM_FLOATS*4)

__global__ void __launch_bounds__(128)
attn_kernel()
{
    extern __shared__ __align__(16) float smem[];
    float* sS = smem;              // [64][LDP]
    float* sO = smem + TBUF;       // [64][LDP]
    float* sK = smem + 2*TBUF;     // [64][LDP]
    float* sV = smem + 3*TBUF;     // [64][LDP]
    float* sM = smem + 4*TBUF;     // [64]
    float* sL = sM + 64;           // [64]

    const int tid = threadIdx.x;
    const int w   = tid >> 5;
    const int i   = 31 - (int)blockIdx.x;   // heavy blocks first
    const int h   = blockIdx.y;
    const int b   = blockIdx.z;

    const size_t head_off = (size_t)(b * HH + h) * TT * DD;
    const float* Qp = g_q + head_off;
    const float* Kp = g_k + head_off;
    const float* Vp = g_v + head_off;

    const int q0 = i * 64;
    const int r0 = w * 16;

    // Stage a 64x64 tile via cp.async (each of 128 threads: 8 x 16B)
    auto stage_tile = [&](const float* src, float* dstbuf, int k0) {
#pragma unroll
        for (int it = 0; it < 8; it++) {
            int idx = tid + it * 128;        // 0..1023
            int row = idx >> 4;              // 0..63
            int c4  = (idx & 15) * 4;        // 0..60
            cp_async16(&dstbuf[row * LDP + c4],
                       &src[(size_t)(k0 + row) * DD + c4]);
        }
    };

    // Preload Q fragments (scaled by 1/sqrt(D) = 0.125)
    FragA qf[8];
#pragma unroll
    for (int kk = 0; kk < 8; kk++) {
        wmma::load_matrix_sync(qf[kk], Qp + (size_t)(q0 + r0) * 64 + kk * 8, 64);
#pragma unroll
        for (int t = 0; t < qf[kk].num_elements; t++)
            qf[kk].x[t] = wmma::__float_to_tf32(qf[kk].x[t] * 0.125f);
    }

    // Init O, m, l; prologue K(0)
    stage_tile(Kp, sK, 0);
    CP_ASYNC_COMMIT();
    for (int idx = tid; idx < 64 * LDP; idx += 128) sO[idx] = 0.0f;
    if (tid < 64) { sM[tid] = -1e30f; sL[tid] = 0.0f; }
    CP_ASYNC_WAIT0();
    __syncthreads();

    for (int j = 0; j <= i; j++) {
        const int k0 = j * 64;

        // ---- S = Q K^T (K from sK, col-major) ----
        FragC sacc[4];
#pragma unroll
        for (int nt = 0; nt < 4; nt++) wmma::fill_fragment(sacc[nt], 0.0f);
#pragma unroll
        for (int kk = 0; kk < 8; kk++) {
#pragma unroll
            for (int nt = 0; nt < 4; nt++) {
                FragBc kb;
                wmma::load_matrix_sync(kb, &sK[(nt * 16) * LDP + kk * 8], LDP);
                to_tf32(kb);
                wmma::mma_sync(sacc[nt], qf[kk], kb, sacc[nt]);
            }
        }
#pragma unroll
        for (int nt = 0; nt < 4; nt++)
            wmma::store_matrix_sync(&sS[r0 * LDP + nt * 16], sacc[nt], LDP,
                                    wmma::mem_row_major);
        __syncthreads();   // [A] sS complete; all sK reads done

        // ---- issue V(j) and K(j+1, clamped) copies ----
        stage_tile(Vp, sV, k0);
        CP_ASYNC_COMMIT();                       // group: V
        {
            int jn = (j + 1 <= i) ? (j + 1) : i; // clamp: valid addr, unused if last
            stage_tile(Kp, sK, jn * 64);
            CP_ASYNC_COMMIT();                   // group: K
        }

        // ---- online softmax (2 threads per row), overlaps both copies ----
        {
            const int row  = tid >> 1;
            const int half = tid & 1;
            const int cb   = half * 32;
            const bool diag = (j == i);
            float* srow = &sS[row * LDP];
            float* orow = &sO[row * LDP];

            float mx = -1e30f;
#pragma unroll
            for (int c = 0; c < 32; c++) {
                int cc = cb + c;
                if (!diag || cc <= row) mx = fmaxf(mx, srow[cc]);
            }
            mx = fmaxf(mx, __shfl_xor_sync(0xffffffffu, mx, 1));

            float m_old = sM[row];
            float m_new = fmaxf(m_old, mx);
            float alpha = __expf(m_old - m_new);

            float sum = 0.0f;
#pragma unroll
            for (int c = 0; c < 32; c++) {
                int cc = cb + c;
                float p = (!diag || cc <= row) ? __expf(srow[cc] - m_new) : 0.0f;
                srow[cc] = p;
                sum += p;
            }
            sum += __shfl_xor_sync(0xffffffffu, sum, 1);

#pragma unroll
            for (int c = 0; c < 32; c++) orow[cb + c] *= alpha;

            if (half == 0) {
                sM[row] = m_new;
                sL[row] = sL[row] * alpha + sum;
            }
        }

        CP_ASYNC_WAIT1();   // V resident (K may still be in flight)
        __syncthreads();    // [B]

        // ---- O += P V (V from sV) ----
        FragC oacc[4];
#pragma unroll
        for (int nt = 0; nt < 4; nt++)
            wmma::load_matrix_sync(oacc[nt], &sO[r0 * LDP + nt * 16], LDP,
                                   wmma::mem_row_major);
#pragma unroll
        for (int kk = 0; kk < 8; kk++) {
            FragA pa;
            wmma::load_matrix_sync(pa, &sS[r0 * LDP + kk * 8], LDP);
            to_tf32(pa);
#pragma unroll
            for (int nt = 0; nt < 4; nt++) {
                FragB vb;
                wmma::load_matrix_sync(vb, &sV[(kk * 8) * LDP + nt * 16], LDP);
                to_tf32(vb);
                wmma::mma_sync(oacc[nt], pa, vb, oacc[nt]);
            }
        }
#pragma unroll
        for (int nt = 0; nt < 4; nt++)
            wmma::store_matrix_sync(&sO[r0 * LDP + nt * 16], oacc[nt], LDP,
                                    wmma::mem_row_major);

        CP_ASYNC_WAIT0();   // K(j+1) resident
        __syncthreads();    // [C]
    }

    // ---- normalize and write y as [B, T, C] ----
    {
        const int row  = tid >> 1;
        const int half = tid & 1;
        const int cb   = half * 32;
        const float inv = 1.0f / sL[row];
        const int t = q0 + row;
        float* dst = g_y + ((size_t)(b * TT + t)) * CC + h * DD;
        float* orow = &sO[row * LDP];
#pragma unroll
        for (int c = 0; c < 32; c++) dst[cb + c] = orow[cb + c] * inv;
    }
}

// ---------------------------------------------------------------------------
extern "C" void kernel_launch(void* const* d_in, const int* in_sizes, int n_in,
                              void* d_out, int out_size)
{
    const float* x  = nullptr;
    const float* Wa = nullptr;
    const float* Wp = nullptr;
    for (int idx = 0; idx < n_in; idx++) {
        if (in_sizes[idx] == MM * CC)        x  = (const float*)d_in[idx];   // 8388608
        else if (in_sizes[idx] == CC * NQKV) Wa = (const float*)d_in[idx];   // 3145728
        else if (in_sizes[idx] == CC * CC)   Wp = (const float*)d_in[idx];   // 1048576
    }
    float* out = (float*)d_out;

    cudaFuncSetAttribute(gemm_kernel,
                         cudaFuncAttributeMaxDynamicSharedMemorySize,
                         GEMM_SMEM_BYTES);
    cudaFuncSetAttribute(attn_kernel,
                         cudaFuncAttributeMaxDynamicSharedMemorySize,
                         ATTN_SMEM_BYTES);

    // 1) QKV projection, scattered into [B,H,T,D]
    gemm_kernel<<<dim3(NQKV / 128, MM / 128), 256, GEMM_SMEM_BYTES>>>(x, Wa, NQKV, nullptr, 0);
    // 2) causal attention -> y [B,T,C]
    attn_kernel<<<dim3(32, HH, BB), 128, ATTN_SMEM_BYTES>>>();
    // 3) output projection (A==nullptr -> reads g_y)
    gemm_kernel<<<dim3(CC / 128, MM / 128), 256, GEMM_SMEM_BYTES>>>(nullptr, Wp, CC, out, 1);
}

// round 16
// speedup vs baseline: 1.0442x; 1.0442x over previous
#include <cuda_runtime.h>
#include <cstdint>
#include <mma.h>
#include <math.h>

using namespace nvcuda;

// Problem constants
#define BB 4
#define TT 2048
#define CC 1024
#define HH 16
#define DD 64
#define MM (BB*TT)          // 8192 rows
#define NQKV (3*CC)         // 3072

// Scratch (device globals; no allocations allowed)
__device__ float g_q[(size_t)BB*HH*TT*DD];
__device__ float g_k[(size_t)BB*HH*TT*DD];
__device__ float g_v[(size_t)BB*HH*TT*DD];
__device__ float g_y[(size_t)MM*CC];

using FragA  = wmma::fragment<wmma::matrix_a, 16,16,8, wmma::precision::tf32, wmma::row_major>;
using FragB  = wmma::fragment<wmma::matrix_b, 16,16,8, wmma::precision::tf32, wmma::row_major>;
using FragBc = wmma::fragment<wmma::matrix_b, 16,16,8, wmma::precision::tf32, wmma::col_major>;
using FragC  = wmma::fragment<wmma::accumulator, 16,16,8, float>;

template <class F>
__device__ __forceinline__ void to_tf32(F& f) {
#pragma unroll
    for (int t = 0; t < f.num_elements; t++) f.x[t] = wmma::__float_to_tf32(f.x[t]);
}

__device__ __forceinline__ void cp_async16(float* smem_dst, const float* gmem_src) {
    uint32_t s = (uint32_t)__cvta_generic_to_shared(smem_dst);
    asm volatile("cp.async.cg.shared.global [%0], [%1], 16;\n" :: "r"(s), "l"(gmem_src));
}
#define CP_ASYNC_COMMIT() asm volatile("cp.async.commit_group;\n" ::: "memory")
#define CP_ASYNC_WAIT0()  asm volatile("cp.async.wait_group 0;\n" ::: "memory")
#define CP_ASYNC_WAIT1()  asm volatile("cp.async.wait_group 1;\n" ::: "memory")

// ---------------------------------------------------------------------------
// GEMM: C[M,N] = A[M,K=1024] * W[K, N] (row-major W, ldb = N)
// mode 0: N=3072, scatter into g_q/g_k/g_v as [B,H,T,D]
// mode 1: N=1024, store to Cout row-major [M, 1024]
// Block tile 128x128, BK=32, 8 warps in 4(m) x 2(n), warp tile 32x64.
// cp.async double-buffered mainloop; one barrier per K-step.
// __launch_bounds__(256, 2): cap regs at 128 so 2 CTAs fit per SM
// (R14 ncu: regs=160 -> 1 CTA/SM, occ=12.5%, tensor pipe 40.8%).
// ---------------------------------------------------------------------------
#define AS_STRIDE 40
#define BS_STRIDE 136
#define AS_BUF (128*AS_STRIDE)           // 5120 floats
#define BS_BUF (32*BS_STRIDE)            // 4352 floats
#define GEMM_SMEM_FLOATS (2*AS_BUF + 2*BS_BUF)
#define GEMM_SMEM_BYTES  (GEMM_SMEM_FLOATS*4)

__global__ void __launch_bounds__(256, 2)
gemm_kernel(const float* __restrict__ A, const float* __restrict__ W,
            int ldb, float* __restrict__ Cout, int mode)
{
    extern __shared__ __align__(16) float gsmem[];
    float* As = gsmem;                   // [2][128][AS_STRIDE]
    float* Bs = gsmem + 2*AS_BUF;        // [2][32][BS_STRIDE]

    const float* Ap = A ? A : g_y;

    const int tid  = threadIdx.x;
    const int lane = tid & 31;
    const int w    = tid >> 5;
    const int wm   = w & 3;
    const int wn   = w >> 2;
    const int m0   = blockIdx.y * 128;
    const int n0   = blockIdx.x * 128;
    const int K    = 1024;

    FragC acc[2][4];
#pragma unroll
    for (int i = 0; i < 2; i++)
#pragma unroll
        for (int j = 0; j < 4; j++) wmma::fill_fragment(acc[i][j], 0.0f);

    const int ar = tid >> 3;
    const int ac = (tid & 7) * 4;
    const int bc = lane * 4;

    auto issue_tile = [&](int kt, int buf) {
        const int k0 = kt * 32;
        float* Ab = As + buf * AS_BUF;
        float* Bb = Bs + buf * BS_BUF;
#pragma unroll
        for (int p = 0; p < 4; p++) {
            cp_async16(&Ab[(ar + 32 * p) * AS_STRIDE + ac],
                       &Ap[(size_t)(m0 + ar + 32 * p) * K + k0 + ac]);
        }
#pragma unroll
        for (int p = 0; p < 4; p++) {
            cp_async16(&Bb[(w + 8 * p) * BS_STRIDE + bc],
                       &W[(size_t)(k0 + w + 8 * p) * ldb + n0 + bc]);
        }
    };

    issue_tile(0, 0);
    CP_ASYNC_COMMIT();
    CP_ASYNC_WAIT0();
    __syncthreads();

    const int NKT = K / 32;
    for (int kt = 0; kt < NKT; kt++) {
        const int cur = kt & 1;

        if (kt + 1 < NKT) {
            issue_tile(kt + 1, cur ^ 1);
            CP_ASYNC_COMMIT();
        }

        float* Ab = As + cur * AS_BUF;
        float* Bb = Bs + cur * BS_BUF;
#pragma unroll
        for (int ks = 0; ks < 4; ks++) {
            FragA af[2];
            FragB bf[4];
#pragma unroll
            for (int i = 0; i < 2; i++) {
                wmma::load_matrix_sync(af[i], &Ab[(wm * 32 + i * 16) * AS_STRIDE + ks * 8], AS_STRIDE);
                to_tf32(af[i]);
            }
#pragma unroll
            for (int j = 0; j < 4; j++) {
                wmma::load_matrix_sync(bf[j], &Bb[(ks * 8) * BS_STRIDE + wn * 64 + j * 16], BS_STRIDE);
                to_tf32(bf[j]);
            }
#pragma unroll
            for (int i = 0; i < 2; i++)
#pragma unroll
                for (int j = 0; j < 4; j++)
                    wmma::mma_sync(acc[i][j], af[i], bf[j], acc[i][j]);
        }

        CP_ASYNC_WAIT0();
        __syncthreads();
    }

    // Epilogue
#pragma unroll
    for (int i = 0; i < 2; i++) {
#pragma unroll
        for (int j = 0; j < 4; j++) {
            int m = m0 + wm * 32 + i * 16;
            int n = n0 + wn * 64 + j * 16;
            if (mode == 1) {
                wmma::store_matrix_sync(&Cout[(size_t)m * 1024 + n], acc[i][j],
                                        1024, wmma::mem_row_major);
            } else {
                int which = n >> 10;          // 0=q 1=k 2=v
                int c = n & 1023;
                int h = c >> 6;
                int d = c & 63;
                int b = m >> 11;
                int t = m & 2047;
                float* base = (which == 0) ? g_q : (which == 1) ? g_k : g_v;
                float* dst = base + ((size_t)(b * HH + h) * TT + t) * DD + d;
                wmma::store_matrix_sync(dst, acc[i][j], 64, wmma::mem_row_major);
            }
        }
    }
}

// ---------------------------------------------------------------------------
// Flash-style causal attention. One block = (b, h, 128-row q tile), 8 warps.
// kv-tile stays 64. vs R13: barriers halved, K/V global traffic halved
// (Q-reuse 2x), 16 warps/SM (2 CTAs x 8 warps, SMEM ~103KB).
// Dynamic SMEM (floats): sS[128][68], sO[128][68], sK[64][68], sV[64][68],
// sM[128], sL[128].
// Pipeline per kv-tile j (j = 0 .. 2i+1):
//   [K(j) resident]  S = Q K^T  -> sS ; barrier A
//   issue cp.async V(j)->sV (group), K(j+1 clamped)->sK (group)
//   softmax on sS/sO (overlaps both copies)
//   wait_group 1 (V resident) ; barrier B
//   O += P V from sV ; wait_group 0 (K resident) ; barrier C
// Mask: element (row, cc) valid iff cc <= row + (q0 - k0); only tiles
// j >= 2i can mask anything (diag flag), j = 2i+1 masks rows < 64 fully
// (sum=0, alpha=1 -> state unchanged; no NaNs since j=0 always runs first).
// ---------------------------------------------------------------------------
#define LDP 68
#define QROWS 128
#define SBUF (QROWS*LDP)       // sS / sO
#define KBUF (64*LDP)          // sK / sV
#define ATTN_SMEM_FLOATS (2*SBUF + 2*KBUF + 2*QROWS)
#define ATTN_SMEM_BYTES  (ATTN_SMEM_FLOATS*4)

__global__ void __launch_bounds__(256)
attn_kernel()
{
    extern __shared__ __align__(16) float smem[];
    float* sS = smem;                       // [128][LDP]
    float* sO = smem + SBUF;                // [128][LDP]
    float* sK = smem + 2*SBUF;              // [64][LDP]
    float* sV = smem + 2*SBUF + KBUF;       // [64][LDP]
    float* sM = smem + 2*SBUF + 2*KBUF;     // [128]
    float* sL = sM + QROWS;                 // [128]

    const int tid = threadIdx.x;
    const int w   = tid >> 5;                // 0..7
    const int i   = 15 - (int)blockIdx.x;    // heavy q-tiles first
    const int h   = blockIdx.y;
    const int b   = blockIdx.z;

    const size_t head_off = (size_t)(b * HH + h) * TT * DD;
    const float* Qp = g_q + head_off;
    const float* Kp = g_k + head_off;
    const float* Vp = g_v + head_off;

    const int q0   = i * QROWS;
    const int r0   = w * 16;                 // warp's 16-row slice of the q tile
    const int jmax = 2 * i + 1;              // last kv tile index

    // Stage a 64x64 tile via cp.async (256 threads: 4 x 16B each)
    auto stage_tile = [&](const float* src, float* dstbuf, int k0) {
#pragma unroll
        for (int it = 0; it < 4; it++) {
            int idx = tid + it * 256;        // 0..1023
            int row = idx >> 4;              // 0..63
            int c4  = (idx & 15) * 4;        // 0..60
            cp_async16(&dstbuf[row * LDP + c4],
                       &src[(size_t)(k0 + row) * DD + c4]);
        }
    };

    // Preload Q fragments (scaled by 1/sqrt(D) = 0.125)
    FragA qf[8];
#pragma unroll
    for (int kk = 0; kk < 8; kk++) {
        wmma::load_matrix_sync(qf[kk], Qp + (size_t)(q0 + r0) * 64 + kk * 8, 64);
#pragma unroll
        for (int t = 0; t < qf[kk].num_elements; t++)
            qf[kk].x[t] = wmma::__float_to_tf32(qf[kk].x[t] * 0.125f);
    }

    // Init O, m, l; prologue K(0)
    stage_tile(Kp, sK, 0);
    CP_ASYNC_COMMIT();
    for (int idx = tid; idx < SBUF; idx += 256) sO[idx] = 0.0f;
    if (tid < QROWS) { sM[tid] = -1e30f; sL[tid] = 0.0f; }
    CP_ASYNC_WAIT0();
    __syncthreads();

    for (int j = 0; j <= jmax; j++) {
        const int k0 = j * 64;

        // ---- S = Q K^T (K from sK, col-major) ----
        FragC sacc[4];
#pragma unroll
        for (int nt = 0; nt < 4; nt++) wmma::fill_fragment(sacc[nt], 0.0f);
#pragma unroll
        for (int kk = 0; kk < 8; kk++) {
#pragma unroll
            for (int nt = 0; nt < 4; nt++) {
                FragBc kb;
                wmma::load_matrix_sync(kb, &sK[(nt * 16) * LDP + kk * 8], LDP);
                to_tf32(kb);
                wmma::mma_sync(sacc[nt], qf[kk], kb, sacc[nt]);
            }
        }
#pragma unroll
        for (int nt = 0; nt < 4; nt++)
            wmma::store_matrix_sync(&sS[r0 * LDP + nt * 16], sacc[nt], LDP,
                                    wmma::mem_row_major);
        __syncthreads();   // [A] sS complete; all sK reads done

        // ---- issue V(j) and K(j+1, clamped) copies ----
        stage_tile(Vp, sV, k0);
        CP_ASYNC_COMMIT();                          // group: V
        {
            int jn = (j + 1 <= jmax) ? (j + 1) : jmax;  // clamp: valid addr
            stage_tile(Kp, sK, jn * 64);
            CP_ASYNC_COMMIT();                      // group: K
        }

        // ---- online softmax (2 threads per row), overlaps both copies ----
        {
            const int row  = tid >> 1;              // 0..127
            const int half = tid & 1;
            const int cb   = half * 32;
            const bool diag = (j >= 2 * i);         // only these tiles mask
            const int lim  = row + q0 - k0;         // valid iff cc <= lim
            float* srow = &sS[row * LDP];
            float* orow = &sO[row * LDP];

            float mx = -1e30f;
#pragma unroll
            for (int c = 0; c < 32; c++) {
                int cc = cb + c;
                if (!diag || cc <= lim) mx = fmaxf(mx, srow[cc]);
            }
            mx = fmaxf(mx, __shfl_xor_sync(0xffffffffu, mx, 1));

            float m_old = sM[row];
            float m_new = fmaxf(m_old, mx);
            float alpha = __expf(m_old - m_new);

            float sum = 0.0f;
#pragma unroll
            for (int c = 0; c < 32; c++) {
                int cc = cb + c;
                float p = (!diag || cc <= lim) ? __expf(srow[cc] - m_new) : 0.0f;
                srow[cc] = p;
                sum += p;
            }
            sum += __shfl_xor_sync(0xffffffffu, sum, 1);

#pragma unroll
            for (int c = 0; c < 32; c++) orow[cb + c] *= alpha;

            if (half == 0) {
                sM[row] = m_new;
                sL[row] = sL[row] * alpha + sum;
            }
        }

        CP_ASYNC_WAIT1();   // V resident (K may still be in flight)
        __syncthreads();    // [B]

        // ---- O += P V (V from sV) ----
        FragC oacc[4];
#pragma unroll
        for (int nt = 0; nt < 4; nt++)
            wmma::load_matrix_sync(oacc[nt], &sO[r0 * LDP + nt * 16], LDP,
                                   wmma::mem_row_major);
#pragma unroll
        for (int kk = 0; kk < 8; kk++) {
            FragA pa;
            wmma::load_matrix_sync(pa, &sS[r0 * LDP + kk * 8], LDP);
            to_tf32(pa);
#pragma unroll
            for (int nt = 0; nt < 4; nt++) {
                FragB vb;
                wmma::load_matrix_sync(vb, &sV[(kk * 8) * LDP + nt * 16], LDP);
                to_tf32(vb);
                wmma::mma_sync(oacc[nt], pa, vb, oacc[nt]);
            }
        }
#pragma unroll
        for (int nt = 0; nt < 4; nt++)
            wmma::store_matrix_sync(&sO[r0 * LDP + nt * 16], oacc[nt], LDP,
                                    wmma::mem_row_major);

        CP_ASYNC_WAIT0();   // K(j+1) resident
        __syncthreads();    // [C]
    }

    // ---- normalize and write y as [B, T, C] ----
    {
        const int row  = tid >> 1;
        const int half = tid & 1;
        const int cb   = half * 32;
        const float inv = 1.0f / sL[row];
        const int t = q0 + row;
        float* dst = g_y + ((size_t)(b * TT + t)) * CC + h * DD;
        float* orow = &sO[row * LDP];
#pragma unroll
        for (int c = 0; c < 32; c++) dst[cb + c] = orow[cb + c] * inv;
    }
}

// ---------------------------------------------------------------------------
extern "C" void kernel_launch(void* const* d_in, const int* in_sizes, int n_in,
                              void* d_out, int out_size)
{
    const float* x  = nullptr;
    const float* Wa = nullptr;
    const float* Wp = nullptr;
    for (int idx = 0; idx < n_in; idx++) {
        if (in_sizes[idx] == MM * CC)        x  = (const float*)d_in[idx];   // 8388608
        else if (in_sizes[idx] == CC * NQKV) Wa = (const float*)d_in[idx];   // 3145728
        else if (in_sizes[idx] == CC * CC)   Wp = (const float*)d_in[idx];   // 1048576
    }
    float* out = (float*)d_out;

    cudaFuncSetAttribute(gemm_kernel,
                         cudaFuncAttributeMaxDynamicSharedMemorySize,
                         GEMM_SMEM_BYTES);
    cudaFuncSetAttribute(attn_kernel,
                         cudaFuncAttributeMaxDynamicSharedMemorySize,
                         ATTN_SMEM_BYTES);

    // 1) QKV projection, scattered into [B,H,T,D]
    gemm_kernel<<<dim3(NQKV / 128, MM / 128), 256, GEMM_SMEM_BYTES>>>(x, Wa, NQKV, nullptr, 0);
    // 2) causal attention -> y [B,T,C]
    attn_kernel<<<dim3(TT / QROWS, HH, BB), 256, ATTN_SMEM_BYTES>>>();
    // 3) output projection (A==nullptr -> reads g_y)
    gemm_kernel<<<dim3(CC / 128, MM / 128), 256, GEMM_SMEM_BYTES>>>(nullptr, Wp, CC, out, 1);
}